// round 14
// baseline (speedup 1.0000x reference)
#include <cuda_runtime.h>
#include <math.h>
#include <stdint.h>

#define Nn 4096
#define Lt 256
#define TLt 128
#define MUc 0.001f
#define Ac 0.999f          /* 1-mu */
#define NM1 4095.0f
#define INV_NM1 (1.0f/4095.0f)
#define EPSF 2.2204460492503131e-16f
#define NNsz ((size_t)Nn*(size_t)Nn)

typedef unsigned long long ull;

// ---- scratch (device globals; no allocations allowed) ----
__device__ __align__(16) uint32_t g_pk[Lt * 128];  // h packed to bits
__device__ float g_rho[Lt];
__device__ float g_inv[Nn];              // 1 / colsum of clip(a)*clip(b)
__device__ float g_aT[NNsz];             // alpha transposed
__device__ float g_bT[NNsz];             // beta transposed

// ---- packed f32x2 helpers ----
__device__ __forceinline__ ull pk2(float lo, float hi) {
    ull r; asm("mov.b64 %0,{%1,%2};" : "=l"(r) : "f"(lo), "f"(hi)); return r;
}
__device__ __forceinline__ void up2(ull v, float& lo, float& hi) {
    asm("mov.b64 {%0,%1},%2;" : "=f"(lo), "=f"(hi) : "l"(v));
}
__device__ __forceinline__ ull ffma2(ull a, ull b, ull c) {
    ull d; asm("fma.rn.f32x2 %0,%1,%2,%3;" : "=l"(d) : "l"(a), "l"(b), "l"(c)); return d;
}
__device__ __forceinline__ ull fmul2(ull a, ull b) {
    ull d; asm("mul.rn.f32x2 %0,%1,%2;" : "=l"(d) : "l"(a), "l"(b)); return d;
}
__device__ __forceinline__ ull fadd2(ull a, ull b) {
    ull d; asm("add.rn.f32x2 %0,%1,%2;" : "=l"(d) : "l"(a), "l"(b)); return d;
}
__device__ __forceinline__ float frcp_fast(float x) {
    float r; asm("rcp.approx.f32 %0,%1;" : "=f"(r) : "f"(x)); return r;
}

// rho[l] = -expm1(-n_e * m[l]),  n_e = 4*10000/4096 = 9.765625
__global__ void k_rho(float* __restrict__ rho, const float* __restrict__ m) {
    int t = threadIdx.x;
    if (t < Lt) rho[t] = -expm1f(-9.765625f * m[t]);
}

// pack h rows into bitmasks: bit (i&31) of word i>>5
__global__ void k_pack(const int* __restrict__ h, uint32_t* __restrict__ pk) {
    const int l = blockIdx.x;
    const int w = threadIdx.x;           // 0..127
    const int* row = h + (size_t)l * Nn + w * 32;
    uint32_t v = 0;
#pragma unroll
    for (int b = 0; b < 32; ++b) v |= ((uint32_t)(row[b] & 1)) << b;
    pk[l * 128 + w] = v;
}

// ---- lean one-barrier block sum of 4 partials (512 threads).
// Stage1: value-splitting butterfly: 6 SHFL for 4 sums.
// Stage2 after bar: 64 scalar partials -> 2 LDS + 3 butterfly + 4 broadcast SHFL.
// sbuf = float[2][64], selected by parity. Result in every thread.
__device__ __forceinline__ float4 blockSum4v2(float s0, float s1, float s2, float s3,
                                              float* sbuf, int t, int par) {
    const int lane = t & 31, w = t >> 5;
    const bool hi16 = (lane & 16) != 0, hi8 = (lane & 8) != 0;
    float tA = __shfl_xor_sync(0xFFFFFFFFu, hi16 ? s0 : s2, 16);
    float tB = __shfl_xor_sync(0xFFFFFFFFu, hi16 ? s1 : s3, 16);
    const float x = hi16 ? (s2 + tA) : (s0 + tA);
    const float y = hi16 ? (s3 + tB) : (s1 + tB);
    float tC = __shfl_xor_sync(0xFFFFFFFFu, hi8 ? x : y, 8);
    float z = (hi8 ? y : x) + tC;
    z += __shfl_xor_sync(0xFFFFFFFFu, z, 4);
    z += __shfl_xor_sync(0xFFFFFFFFu, z, 2);
    z += __shfl_xor_sync(0xFFFFFFFFu, z, 1);
    float* buf = sbuf + (par << 6);
    if ((lane & 7) == 0) buf[(w << 2) + (lane >> 3)] = z;
    __syncthreads();
    float v = buf[lane] + buf[lane + 32];          // idx = w*4+c, c = idx&3
    v += __shfl_xor_sync(0xFFFFFFFFu, v, 4);
    v += __shfl_xor_sync(0xFFFFFFFFu, v, 8);
    v += __shfl_xor_sync(0xFFFFFFFFu, v, 16);
    float4 r;
    r.x = __shfl_sync(0xFFFFFFFFu, v, 0, 4);
    r.y = __shfl_sync(0xFFFFFFFFu, v, 1, 4);
    r.z = __shfl_sync(0xFFFFFFFFu, v, 2, 4);
    r.w = __shfl_sync(0xFFFFFFFFu, v, 3, 4);
    return r;
}

// diag fix: subtract diag values from packed sums AND zero state lanes.
__device__ __forceinline__ void diag_fix_fwd(ull& a0, ull& a1, ull& b2, ull& b3,
                                             ull& s0, ull& s1) {
    float lo, hi, sl, sh;
    up2(s0, sl, sh);
    up2(a0, lo, hi); sl -= lo; a0 = pk2(0.f, hi);
    up2(a1, lo, hi); sh -= hi; a1 = pk2(lo, 0.f);
    s0 = pk2(sl, sh);
    up2(s1, sl, sh);
    up2(b2, lo, hi); sl -= lo; b2 = pk2(0.f, hi);
    up2(b3, lo, hi); sh -= hi; b3 = pk2(lo, 0.f);
    s1 = pk2(sl, sh);
}
__device__ __forceinline__ void diag_zero(ull& a0, ull& a1, ull& b2, ull& b3) {
    a0 &= 0xFFFFFFFF00000000ull;  // zero lo lane
    a1 &= 0x00000000FFFFFFFFull;  // zero hi lane
    b2 &= 0xFFFFFFFF00000000ull;
    b3 &= 0x00000000FFFFFFFFull;
}

// transposed final store: thread owns rows r0..r0+7, cols j0..j0+3
__device__ __forceinline__ void store_T(float* __restrict__ xT, const ull st[8][2],
                                        int j0, int r0) {
#pragma unroll
    for (int c = 0; c < 4; ++c) {
        float v[8];
#pragma unroll
        for (int r = 0; r < 8; ++r) {
            float lo, hi; up2(st[r][c >> 1], lo, hi);
            v[r] = (c & 1) ? hi : lo;
        }
        float* base = xT + (size_t)(j0 + c) * Nn + r0;
        *(float4*)base       = make_float4(v[0], v[1], v[2], v[3]);
        *(float4*)(base + 4) = make_float4(v[4], v[5], v[6], v[7]);
    }
}

// ---------------- forward body: 129 steps resident in registers ----------------
// (1-step lagged: tot from the call at step s-1 feeds wp of step s)
__device__ __forceinline__ void fwd_body(float* __restrict__ aT, int blk,
                                         float* sbuf, float* srho) {
    const int t = threadIdx.x;
    const int j0 = blk << 2;
    const int r0 = t << 3;
    if (t < Lt) srho[t] = g_rho[t];

    ull st[8][2];
#pragma unroll
    for (int r = 0; r < 8; ++r) { st[r][0] = 0ull; st[r][1] = 0ull; }
    float4 tot = make_float4(1.f, 1.f, 1.f, 1.f);   // dummy; step0 uses w=0
    __syncthreads();

    const int wWord = r0 >> 5, wSh = r0 & 31;
    const int jWord = j0 >> 5, jSh = j0 & 31;
    const bool isDiagT = (t == (j0 >> 3));
    const bool diagHi = (j0 & 7) != 0;   // diag rows 4..7 vs 0..3

    for (int step = 0; step <= TLt; ++step) {
        const uint32_t* row = g_pk + step * 128;
        const uint32_t hb = __ldg(row + wWord) >> wSh;
        const uint32_t hj = (__ldg(row + jWord) >> jSh) & 0xFu;

        float wv, cst;
        if (step == 0) { wv = 0.0f; cst = INV_NM1; }
        else { const float r = srho[step - 1]; wv = 1.0f - r; cst = r * INV_NM1; }

        const float e0a = (hj & 1u) ? MUc : Ac, e1a = (hj & 1u) ? Ac : MUc;
        const float e0b = (hj & 2u) ? MUc : Ac, e1b = (hj & 2u) ? Ac : MUc;
        const float e0c = (hj & 4u) ? MUc : Ac, e1c = (hj & 4u) ? Ac : MUc;
        const float e0d = (hj & 8u) ? MUc : Ac, e1d = (hj & 8u) ? Ac : MUc;
        const ull E0p0 = pk2(e0a, e0b), E1p0 = pk2(e1a, e1b);
        const ull E0p1 = pk2(e0c, e0d), E1p1 = pk2(e1c, e1d);
        const ull wp0 = pk2(wv * frcp_fast(tot.x), wv * frcp_fast(tot.y));
        const ull wp1 = pk2(wv * frcp_fast(tot.z), wv * frcp_fast(tot.w));
        const ull cstp = pk2(cst, cst);

        // dual accumulators: halve the serial fadd2 chain depth
        ull sm0a = 0ull, sm0b = 0ull, sm1a = 0ull, sm1b = 0ull;
#pragma unroll
        for (int r = 0; r < 8; ++r) {
            const bool hi = (hb >> r) & 1u;
            const ull ea = hi ? E1p0 : E0p0;
            const ull eb = hi ? E1p1 : E0p1;
            const ull o0 = fmul2(ffma2(st[r][0], wp0, cstp), ea);
            const ull o1 = fmul2(ffma2(st[r][1], wp1, cstp), eb);
            st[r][0] = o0; st[r][1] = o1;
            if (r & 1) { sm0b = fadd2(sm0b, o0); sm1b = fadd2(sm1b, o1); }
            else       { sm0a = fadd2(sm0a, o0); sm1a = fadd2(sm1a, o1); }
        }
        ull sm0 = fadd2(sm0a, sm0b), sm1 = fadd2(sm1a, sm1b);
        if (isDiagT) {
            if (diagHi) diag_fix_fwd(st[4][0], st[5][0], st[6][1], st[7][1], sm0, sm1);
            else        diag_fix_fwd(st[0][0], st[1][0], st[2][1], st[3][1], sm0, sm1);
        }
        if (step < TLt) {
            float a0, a1, a2, a3;
            up2(sm0, a0, a1); up2(sm1, a2, a3);
            tot = blockSum4v2(a0, a1, a2, a3, sbuf, t, step & 1);
        }
    }
    store_T(aT, st, j0, r0);
}

// ---------------- backward body: u-state (u = theta o beta), deferred K --------
// u_k = theta_k o (K_{k-1} u_{k-1} + r_{k-1}); T_k = sum_{i!=j} u_k (pushed,
// consumed next step); final beta = K_last*u + r_last, diag zeroed.
__device__ __forceinline__ void bwd_body(float* __restrict__ bT, int blk,
                                         float* sbuf, float* srho) {
    const int t = threadIdx.x;
    const int j0 = blk << 2;
    const int r0 = t << 3;
    if (t < Lt) srho[t] = g_rho[t];

    ull st[8][2];
    const ull one2 = pk2(1.0f, 1.0f);
#pragma unroll
    for (int r = 0; r < 8; ++r) { st[r][0] = one2; st[r][1] = one2; }
    __syncthreads();

    const int wWord = r0 >> 5, wSh = r0 & 31;
    const int jWord = j0 >> 5, jSh = j0 & 31;
    const bool isDiagT = (t == (j0 >> 3));
    const bool diagHi = (j0 & 7) != 0;

    ull kp0 = 0ull, kp1 = 0ull;   // k=0: v = 0*st + 1  (beta_0 = 1 offdiag)
    ull rp = one2;
    const int NB = Lt - 1 - TLt;  // 127
    for (int k = 0; k < NB; ++k) {
        const uint32_t* row = g_pk + (Lt - 1 - k) * 128;
        const uint32_t hb = __ldg(row + wWord) >> wSh;
        const uint32_t hj = (__ldg(row + jWord) >> jSh) & 0xFu;

        const float e0a = (hj & 1u) ? MUc : Ac, e1a = (hj & 1u) ? Ac : MUc;
        const float e0b = (hj & 2u) ? MUc : Ac, e1b = (hj & 2u) ? Ac : MUc;
        const float e0c = (hj & 4u) ? MUc : Ac, e1c = (hj & 4u) ? Ac : MUc;
        const float e0d = (hj & 8u) ? MUc : Ac, e1d = (hj & 8u) ? Ac : MUc;
        const ull E0p0 = pk2(e0a, e0b), E1p0 = pk2(e1a, e1b);
        const ull E0p1 = pk2(e0c, e0d), E1p1 = pk2(e1c, e1d);

        ull sm0a = 0ull, sm0b = 0ull, sm1a = 0ull, sm1b = 0ull;
#pragma unroll
        for (int r = 0; r < 8; ++r) {
            const bool hi = (hb >> r) & 1u;
            const ull ea = hi ? E1p0 : E0p0;
            const ull eb = hi ? E1p1 : E0p1;
            const ull u0 = fmul2(ea, ffma2(st[r][0], kp0, rp));
            const ull u1 = fmul2(eb, ffma2(st[r][1], kp1, rp));
            st[r][0] = u0; st[r][1] = u1;
            if (r & 1) { sm0b = fadd2(sm0b, u0); sm1b = fadd2(sm1b, u1); }
            else       { sm0a = fadd2(sm0a, u0); sm1a = fadd2(sm1a, u1); }
        }
        ull sm0 = fadd2(sm0a, sm0b), sm1 = fadd2(sm1a, sm1b);
        if (isDiagT) {
            if (diagHi) diag_fix_fwd(st[4][0], st[5][0], st[6][1], st[7][1], sm0, sm1);
            else        diag_fix_fwd(st[0][0], st[1][0], st[2][1], st[3][1], sm0, sm1);
        }
        float a0, a1, a2, a3;
        up2(sm0, a0, a1); up2(sm1, a2, a3);
        const float4 tot = blockSum4v2(a0, a1, a2, a3, sbuf, t, k & 1);

        const float rr = srho[Lt - 2 - k];
        const float ks = (1.0f - rr) * NM1;
        kp0 = pk2(ks * frcp_fast(tot.x), ks * frcp_fast(tot.y));
        kp1 = pk2(ks * frcp_fast(tot.z), ks * frcp_fast(tot.w));
        rp = pk2(rr, rr);
    }
    // final: beta = K_last*u + r_last; zero diag; store
#pragma unroll
    for (int r = 0; r < 8; ++r) {
        st[r][0] = ffma2(st[r][0], kp0, rp);
        st[r][1] = ffma2(st[r][1], kp1, rp);
    }
    if (isDiagT) {
        if (diagHi) diag_zero(st[4][0], st[5][0], st[6][1], st[7][1]);
        else        diag_zero(st[0][0], st[1][0], st[2][1], st[3][1]);
    }
    store_T(bT, st, j0, r0);
}

// merged, INTERLEAVED: even blocks run forward, odd run backward, so each SM
// hosts one fwd + one bwd block whose barrier phases drift apart — the other
// block's warps fill the issue slots while this one waits at __syncthreads.
__global__ void __launch_bounds__(512, 2) k_main(float* __restrict__ aT,
                                                 float* __restrict__ bT) {
    __shared__ __align__(16) float sbuf[128];   // [2 parities][64 partials]
    __shared__ float srho[Lt];
    if ((blockIdx.x & 1) == 0) fwd_body(aT, blockIdx.x >> 1, sbuf, srho);
    else                       bwd_body(bT, blockIdx.x >> 1, sbuf, srho);
}

// column sums of clip(a)*clip(b) -> inv[j]; block owns 4 rows of a^T/b^T
__global__ void __launch_bounds__(512, 2) k_colsum(const float* __restrict__ aT,
                                                   const float* __restrict__ bT,
                                                   float* __restrict__ inv) {
    __shared__ float4 swarp[16];
    const int t = threadIdx.x;
    const int j0 = blockIdx.x << 2;
    float s[4] = {0.f, 0.f, 0.f, 0.f};
#pragma unroll
    for (int jj = 0; jj < 4; ++jj) {
        const float4* a4 = (const float4*)aT + (size_t)(j0 + jj) * 1024;
        const float4* b4 = (const float4*)bT + (size_t)(j0 + jj) * 1024;
#pragma unroll
        for (int k2 = 0; k2 < 2; ++k2) {
            const int idx = t + (k2 << 9);
            const float4 av = __ldg(a4 + idx);
            const float4 bv = __ldg(b4 + idx);
            s[jj] += __saturatef(av.x) * __saturatef(bv.x)
                   + __saturatef(av.y) * __saturatef(bv.y)
                   + __saturatef(av.z) * __saturatef(bv.z)
                   + __saturatef(av.w) * __saturatef(bv.w);
        }
    }
#pragma unroll
    for (int off = 16; off; off >>= 1) {
        s[0] += __shfl_xor_sync(0xFFFFFFFFu, s[0], off);
        s[1] += __shfl_xor_sync(0xFFFFFFFFu, s[1], off);
        s[2] += __shfl_xor_sync(0xFFFFFFFFu, s[2], off);
        s[3] += __shfl_xor_sync(0xFFFFFFFFu, s[3], off);
    }
    if ((t & 31) == 0) swarp[t >> 5] = make_float4(s[0], s[1], s[2], s[3]);
    __syncthreads();
    if (t == 0) {
        float4 v = swarp[0];
#pragma unroll
        for (int w = 1; w < 16; ++w) {
            float4 q = swarp[w];
            v.x += q.x; v.y += q.y; v.z += q.z; v.w += q.w;
        }
        inv[j0] = 1.0f / v.x; inv[j0 + 1] = 1.0f / v.y;
        inv[j0 + 2] = 1.0f / v.z; inv[j0 + 3] = 1.0f / v.w;
    }
}

// fused epilogue: p + d + alpha/beta std-layout, all from aT/bT tiles.
__global__ void k_out(const float* __restrict__ aT, const float* __restrict__ bT,
                      const float* __restrict__ inv,
                      float* __restrict__ p, float* __restrict__ d,
                      float* __restrict__ aStd, float* __restrict__ bStd) {
    const int bi = blockIdx.y, bj = blockIdx.x;
    if (bj < bi) return;
    __shared__ float PA[32][33], PB[32][33];
    __shared__ float AA[32][33], BA[32][33];
    __shared__ float AB[32][33], BB[32][33];
    const int tx = threadIdx.x & 31;
    const int ty0 = threadIdx.x >> 5;   // 0..7
    const bool diagBlk = (bi == bj);
#pragma unroll
    for (int k2 = 0; k2 < 4; ++k2) {
        const int y = ty0 + (k2 << 3);
        const int ja = (bi << 5) + y;
        const size_t offA = (size_t)ja * Nn + (bj << 5) + tx;
        const float av = __ldg(aT + offA);
        const float bv = __ldg(bT + offA);
        AA[y][tx] = av; BA[y][tx] = bv;
        PA[y][tx] = __saturatef(av) * __saturatef(bv) * __ldg(inv + ja);
        if (!diagBlk) {
            const int jb = (bj << 5) + y;
            const size_t offB = (size_t)jb * Nn + (bi << 5) + tx;
            const float av2 = __ldg(aT + offB);
            const float bv2 = __ldg(bT + offB);
            AB[y][tx] = av2; BB[y][tx] = bv2;
            PB[y][tx] = __saturatef(av2) * __saturatef(bv2) * __ldg(inv + jb);
        }
    }
    __syncthreads();
#pragma unroll
    for (int k2 = 0; k2 < 4; ++k2) {
        const int y = ty0 + (k2 << 3);
        const size_t o1 = (size_t)((bj << 5) + y) * Nn + (bi << 5) + tx;
        p[o1] = PA[tx][y];
        if (aStd) { aStd[o1] = AA[tx][y]; bStd[o1] = BA[tx][y]; }
        if (!diagBlk) {
            const size_t o2 = (size_t)((bi << 5) + y) * Nn + (bj << 5) + tx;
            p[o2] = PB[tx][y];
            if (aStd) { aStd[o2] = AB[tx][y]; bStd[o2] = BB[tx][y]; }
        }
    }
    if (d == nullptr) return;
    __syncthreads();
#pragma unroll
    for (int k2 = 0; k2 < 4; ++k2) {
        const int y = ty0 + (k2 << 3);
        PA[y][tx] = __logf(fmaxf(PA[y][tx], EPSF));
        if (!diagBlk) PB[y][tx] = __logf(fmaxf(PB[y][tx], EPSF));
    }
    __syncthreads();
    float (*LB)[33] = diagBlk ? PA : PB;
#pragma unroll
    for (int k2 = 0; k2 < 4; ++k2) {
        const int y = ty0 + (k2 << 3);
        float dv = -0.5f * (LB[tx][y] + PA[y][tx]);
        if (diagBlk && y == tx) dv = 0.0f;
        d[(size_t)((bi << 5) + y) * Nn + (bj << 5) + tx] = dv;
        if (!diagBlk)
            d[(size_t)((bj << 5) + y) * Nn + (bi << 5) + tx]
                = -0.5f * (PA[tx][y] + LB[y][tx]);
    }
}

extern "C" void kernel_launch(void* const* d_in, const int* in_sizes, int n_in,
                              void* d_out, int out_size) {
    const int* h = (const int*)d_in[0];
    const float* m = (const float*)d_in[1];
    float* out = (float*)d_out;

    void* sym;
    uint32_t* pk; float *rho, *aT, *bT, *inv;
    cudaGetSymbolAddress(&sym, g_pk);  pk  = (uint32_t*)sym;
    cudaGetSymbolAddress(&sym, g_rho); rho = (float*)sym;
    cudaGetSymbolAddress(&sym, g_aT);  aT  = (float*)sym;
    cudaGetSymbolAddress(&sym, g_bT);  bT  = (float*)sym;
    cudaGetSymbolAddress(&sym, g_inv); inv = (float*)sym;

    float *pOut, *dOut, *alphaStd, *betaStd;
    size_t osz = (size_t)out_size;
    if (osz >= 4 * NNsz) {
        pOut = out; dOut = out + NNsz;
        alphaStd = out + 2 * NNsz; betaStd = out + 3 * NNsz;
    } else if (osz >= 2 * NNsz) {
        pOut = out; dOut = out + NNsz; alphaStd = nullptr; betaStd = nullptr;
    } else {
        pOut = out; dOut = nullptr; alphaStd = nullptr; betaStd = nullptr;
    }

    k_rho<<<1, 256>>>(rho, m);
    k_pack<<<Lt, 128>>>(h, pk);
    k_main<<<2048, 512>>>(aT, bT);
    k_colsum<<<Nn / 4, 512>>>(aT, bT, inv);
    dim3 g2(Nn / 32, Nn / 32);
    k_out<<<g2, 256>>>(aT, bT, inv, pOut, dOut, alphaStd, betaStd);
}

// round 15
// speedup vs baseline: 1.0058x; 1.0058x over previous
#include <cuda_runtime.h>
#include <math.h>
#include <stdint.h>

#define Nn 4096
#define Lt 256
#define TLt 128
#define MUc 0.001f
#define Ac 0.999f          /* 1-mu */
#define NM1 4095.0f
#define INV_NM1 (1.0f/4095.0f)
#define EPSF 2.2204460492503131e-16f
#define NNsz ((size_t)Nn*(size_t)Nn)

typedef unsigned long long ull;

// ---- scratch (device globals; no allocations allowed) ----
__device__ __align__(16) uint32_t g_pk[Lt * 128];  // h packed to bits
__device__ float g_rho[Lt];
__device__ float g_inv[Nn];              // 1 / colsum of clip(a)*clip(b)
__device__ float g_aT[NNsz];             // alpha transposed
__device__ float g_bT[NNsz];             // beta transposed

// ---- packed f32x2 helpers ----
__device__ __forceinline__ ull pk2(float lo, float hi) {
    ull r; asm("mov.b64 %0,{%1,%2};" : "=l"(r) : "f"(lo), "f"(hi)); return r;
}
__device__ __forceinline__ void up2(ull v, float& lo, float& hi) {
    asm("mov.b64 {%0,%1},%2;" : "=f"(lo), "=f"(hi) : "l"(v));
}
__device__ __forceinline__ ull ffma2(ull a, ull b, ull c) {
    ull d; asm("fma.rn.f32x2 %0,%1,%2,%3;" : "=l"(d) : "l"(a), "l"(b), "l"(c)); return d;
}
__device__ __forceinline__ ull fmul2(ull a, ull b) {
    ull d; asm("mul.rn.f32x2 %0,%1,%2;" : "=l"(d) : "l"(a), "l"(b)); return d;
}
__device__ __forceinline__ ull fadd2(ull a, ull b) {
    ull d; asm("add.rn.f32x2 %0,%1,%2;" : "=l"(d) : "l"(a), "l"(b)); return d;
}
__device__ __forceinline__ float frcp_fast(float x) {
    float r; asm("rcp.approx.f32 %0,%1;" : "=f"(r) : "f"(x)); return r;
}

// rho[l] = -expm1(-n_e * m[l]),  n_e = 4*10000/4096 = 9.765625
__global__ void k_rho(float* __restrict__ rho, const float* __restrict__ m) {
    int t = threadIdx.x;
    if (t < Lt) rho[t] = -expm1f(-9.765625f * m[t]);
}

// pack h rows into bitmasks: bit (i&31) of word i>>5
__global__ void k_pack(const int* __restrict__ h, uint32_t* __restrict__ pk) {
    const int l = blockIdx.x;
    const int w = threadIdx.x;           // 0..127
    const int* row = h + (size_t)l * Nn + w * 32;
    uint32_t v = 0;
#pragma unroll
    for (int b = 0; b < 32; ++b) v |= ((uint32_t)(row[b] & 1)) << b;
    pk[l * 128 + w] = v;
}

// ---- lean one-barrier block sum of 4 partials (512 threads).
// Stage1: value-splitting butterfly: 6 SHFL for 4 sums.
// Stage2 after bar: 64 scalar partials -> 2 LDS + 3 butterfly + 4 broadcast SHFL.
// sbuf = float[2][64], selected by parity. Result in every thread.
__device__ __forceinline__ float4 blockSum4v2(float s0, float s1, float s2, float s3,
                                              float* sbuf, int t, int par) {
    const int lane = t & 31, w = t >> 5;
    const bool hi16 = (lane & 16) != 0, hi8 = (lane & 8) != 0;
    float tA = __shfl_xor_sync(0xFFFFFFFFu, hi16 ? s0 : s2, 16);
    float tB = __shfl_xor_sync(0xFFFFFFFFu, hi16 ? s1 : s3, 16);
    const float x = hi16 ? (s2 + tA) : (s0 + tA);
    const float y = hi16 ? (s3 + tB) : (s1 + tB);
    float tC = __shfl_xor_sync(0xFFFFFFFFu, hi8 ? x : y, 8);
    float z = (hi8 ? y : x) + tC;
    z += __shfl_xor_sync(0xFFFFFFFFu, z, 4);
    z += __shfl_xor_sync(0xFFFFFFFFu, z, 2);
    z += __shfl_xor_sync(0xFFFFFFFFu, z, 1);
    float* buf = sbuf + (par << 6);
    if ((lane & 7) == 0) buf[(w << 2) + (lane >> 3)] = z;
    __syncthreads();
    float v = buf[lane] + buf[lane + 32];          // idx = w*4+c, c = idx&3
    v += __shfl_xor_sync(0xFFFFFFFFu, v, 4);
    v += __shfl_xor_sync(0xFFFFFFFFu, v, 8);
    v += __shfl_xor_sync(0xFFFFFFFFu, v, 16);
    float4 r;
    r.x = __shfl_sync(0xFFFFFFFFu, v, 0, 4);
    r.y = __shfl_sync(0xFFFFFFFFu, v, 1, 4);
    r.z = __shfl_sync(0xFFFFFFFFu, v, 2, 4);
    r.w = __shfl_sync(0xFFFFFFFFu, v, 3, 4);
    return r;
}

// diag fix: subtract diag values from packed sums AND zero state lanes.
__device__ __forceinline__ void diag_fix_fwd(ull& a0, ull& a1, ull& b2, ull& b3,
                                             ull& s0, ull& s1) {
    float lo, hi, sl, sh;
    up2(s0, sl, sh);
    up2(a0, lo, hi); sl -= lo; a0 = pk2(0.f, hi);
    up2(a1, lo, hi); sh -= hi; a1 = pk2(lo, 0.f);
    s0 = pk2(sl, sh);
    up2(s1, sl, sh);
    up2(b2, lo, hi); sl -= lo; b2 = pk2(0.f, hi);
    up2(b3, lo, hi); sh -= hi; b3 = pk2(lo, 0.f);
    s1 = pk2(sl, sh);
}
__device__ __forceinline__ void diag_zero(ull& a0, ull& a1, ull& b2, ull& b3) {
    a0 &= 0xFFFFFFFF00000000ull;  // zero lo lane
    a1 &= 0x00000000FFFFFFFFull;  // zero hi lane
    b2 &= 0xFFFFFFFF00000000ull;
    b3 &= 0x00000000FFFFFFFFull;
}

// transposed final store: thread owns rows r0..r0+7, cols j0..j0+3
__device__ __forceinline__ void store_T(float* __restrict__ xT, const ull st[8][2],
                                        int j0, int r0) {
#pragma unroll
    for (int c = 0; c < 4; ++c) {
        float v[8];
#pragma unroll
        for (int r = 0; r < 8; ++r) {
            float lo, hi; up2(st[r][c >> 1], lo, hi);
            v[r] = (c & 1) ? hi : lo;
        }
        float* base = xT + (size_t)(j0 + c) * Nn + r0;
        *(float4*)base       = make_float4(v[0], v[1], v[2], v[3]);
        *(float4*)(base + 4) = make_float4(v[4], v[5], v[6], v[7]);
    }
}

// ---------------- forward body: 129 steps resident in registers ----------------
// (1-step lagged: tot from the call at step s-1 feeds wp of step s)
__device__ __forceinline__ void fwd_body(float* __restrict__ aT, int blk,
                                         float* sbuf, float* srho) {
    const int t = threadIdx.x;
    const int j0 = blk << 2;
    const int r0 = t << 3;
    if (t < Lt) srho[t] = g_rho[t];

    ull st[8][2];
#pragma unroll
    for (int r = 0; r < 8; ++r) { st[r][0] = 0ull; st[r][1] = 0ull; }
    float4 tot = make_float4(1.f, 1.f, 1.f, 1.f);   // dummy; step0 uses w=0
    __syncthreads();

    const int wWord = r0 >> 5, wSh = r0 & 31;
    const int jWord = j0 >> 5, jSh = j0 & 31;
    const bool isDiagT = (t == (j0 >> 3));
    const bool diagHi = (j0 & 7) != 0;   // diag rows 4..7 vs 0..3

    for (int step = 0; step <= TLt; ++step) {
        const uint32_t* row = g_pk + step * 128;
        const uint32_t hb = __ldg(row + wWord) >> wSh;
        const uint32_t hj = (__ldg(row + jWord) >> jSh) & 0xFu;

        float wv, cst;
        if (step == 0) { wv = 0.0f; cst = INV_NM1; }
        else { const float r = srho[step - 1]; wv = 1.0f - r; cst = r * INV_NM1; }

        const float e0a = (hj & 1u) ? MUc : Ac, e1a = (hj & 1u) ? Ac : MUc;
        const float e0b = (hj & 2u) ? MUc : Ac, e1b = (hj & 2u) ? Ac : MUc;
        const float e0c = (hj & 4u) ? MUc : Ac, e1c = (hj & 4u) ? Ac : MUc;
        const float e0d = (hj & 8u) ? MUc : Ac, e1d = (hj & 8u) ? Ac : MUc;
        const ull E0p0 = pk2(e0a, e0b), E1p0 = pk2(e1a, e1b);
        const ull E0p1 = pk2(e0c, e0d), E1p1 = pk2(e1c, e1d);
        const ull wp0 = pk2(wv * frcp_fast(tot.x), wv * frcp_fast(tot.y));
        const ull wp1 = pk2(wv * frcp_fast(tot.z), wv * frcp_fast(tot.w));
        const ull cstp = pk2(cst, cst);

        // dual accumulators: halve the serial fadd2 chain depth
        ull sm0a = 0ull, sm0b = 0ull, sm1a = 0ull, sm1b = 0ull;
#pragma unroll
        for (int r = 0; r < 8; ++r) {
            const bool hi = (hb >> r) & 1u;
            const ull ea = hi ? E1p0 : E0p0;
            const ull eb = hi ? E1p1 : E0p1;
            const ull o0 = fmul2(ffma2(st[r][0], wp0, cstp), ea);
            const ull o1 = fmul2(ffma2(st[r][1], wp1, cstp), eb);
            st[r][0] = o0; st[r][1] = o1;
            if (r & 1) { sm0b = fadd2(sm0b, o0); sm1b = fadd2(sm1b, o1); }
            else       { sm0a = fadd2(sm0a, o0); sm1a = fadd2(sm1a, o1); }
        }
        ull sm0 = fadd2(sm0a, sm0b), sm1 = fadd2(sm1a, sm1b);
        if (isDiagT) {
            if (diagHi) diag_fix_fwd(st[4][0], st[5][0], st[6][1], st[7][1], sm0, sm1);
            else        diag_fix_fwd(st[0][0], st[1][0], st[2][1], st[3][1], sm0, sm1);
        }
        if (step < TLt) {
            float a0, a1, a2, a3;
            up2(sm0, a0, a1); up2(sm1, a2, a3);
            tot = blockSum4v2(a0, a1, a2, a3, sbuf, t, step & 1);
        }
    }
    store_T(aT, st, j0, r0);
}

// ---------------- backward body: u-state (u = theta o beta), deferred K --------
// u_k = theta_k o (K_{k-1} u_{k-1} + r_{k-1}); T_k = sum_{i!=j} u_k (pushed,
// consumed next step); final beta = K_last*u + r_last, diag zeroed.
__device__ __forceinline__ void bwd_body(float* __restrict__ bT, int blk,
                                         float* sbuf, float* srho) {
    const int t = threadIdx.x;
    const int j0 = blk << 2;
    const int r0 = t << 3;
    if (t < Lt) srho[t] = g_rho[t];

    ull st[8][2];
    const ull one2 = pk2(1.0f, 1.0f);
#pragma unroll
    for (int r = 0; r < 8; ++r) { st[r][0] = one2; st[r][1] = one2; }
    __syncthreads();

    const int wWord = r0 >> 5, wSh = r0 & 31;
    const int jWord = j0 >> 5, jSh = j0 & 31;
    const bool isDiagT = (t == (j0 >> 3));
    const bool diagHi = (j0 & 7) != 0;

    ull kp0 = 0ull, kp1 = 0ull;   // k=0: v = 0*st + 1  (beta_0 = 1 offdiag)
    ull rp = one2;
    const int NB = Lt - 1 - TLt;  // 127
    for (int k = 0; k < NB; ++k) {
        const uint32_t* row = g_pk + (Lt - 1 - k) * 128;
        const uint32_t hb = __ldg(row + wWord) >> wSh;
        const uint32_t hj = (__ldg(row + jWord) >> jSh) & 0xFu;

        const float e0a = (hj & 1u) ? MUc : Ac, e1a = (hj & 1u) ? Ac : MUc;
        const float e0b = (hj & 2u) ? MUc : Ac, e1b = (hj & 2u) ? Ac : MUc;
        const float e0c = (hj & 4u) ? MUc : Ac, e1c = (hj & 4u) ? Ac : MUc;
        const float e0d = (hj & 8u) ? MUc : Ac, e1d = (hj & 8u) ? Ac : MUc;
        const ull E0p0 = pk2(e0a, e0b), E1p0 = pk2(e1a, e1b);
        const ull E0p1 = pk2(e0c, e0d), E1p1 = pk2(e1c, e1d);

        ull sm0a = 0ull, sm0b = 0ull, sm1a = 0ull, sm1b = 0ull;
#pragma unroll
        for (int r = 0; r < 8; ++r) {
            const bool hi = (hb >> r) & 1u;
            const ull ea = hi ? E1p0 : E0p0;
            const ull eb = hi ? E1p1 : E0p1;
            const ull u0 = fmul2(ea, ffma2(st[r][0], kp0, rp));
            const ull u1 = fmul2(eb, ffma2(st[r][1], kp1, rp));
            st[r][0] = u0; st[r][1] = u1;
            if (r & 1) { sm0b = fadd2(sm0b, u0); sm1b = fadd2(sm1b, u1); }
            else       { sm0a = fadd2(sm0a, u0); sm1a = fadd2(sm1a, u1); }
        }
        ull sm0 = fadd2(sm0a, sm0b), sm1 = fadd2(sm1a, sm1b);
        if (isDiagT) {
            if (diagHi) diag_fix_fwd(st[4][0], st[5][0], st[6][1], st[7][1], sm0, sm1);
            else        diag_fix_fwd(st[0][0], st[1][0], st[2][1], st[3][1], sm0, sm1);
        }
        float a0, a1, a2, a3;
        up2(sm0, a0, a1); up2(sm1, a2, a3);
        const float4 tot = blockSum4v2(a0, a1, a2, a3, sbuf, t, k & 1);

        const float rr = srho[Lt - 2 - k];
        const float ks = (1.0f - rr) * NM1;
        kp0 = pk2(ks * frcp_fast(tot.x), ks * frcp_fast(tot.y));
        kp1 = pk2(ks * frcp_fast(tot.z), ks * frcp_fast(tot.w));
        rp = pk2(rr, rr);
    }
    // final: beta = K_last*u + r_last; zero diag; store
#pragma unroll
    for (int r = 0; r < 8; ++r) {
        st[r][0] = ffma2(st[r][0], kp0, rp);
        st[r][1] = ffma2(st[r][1], kp1, rp);
    }
    if (isDiagT) {
        if (diagHi) diag_zero(st[4][0], st[5][0], st[6][1], st[7][1]);
        else        diag_zero(st[0][0], st[1][0], st[2][1], st[3][1]);
    }
    store_T(bT, st, j0, r0);
}

// merged, chunk-interleaved by 128: flavor = (b>>7)&1, so co-resident blocks
// s and s+148 (contiguous-modular placement) get DIFFERENT flavors on ~87% of
// SMs — fwd and bwd bodies drift anti-phase and hide each other's barriers.
// 16 chunks x 128 = 2048; 8 fwd chunks + 8 bwd chunks = 1024 each.
__global__ void __launch_bounds__(512, 2) k_main(float* __restrict__ aT,
                                                 float* __restrict__ bT) {
    __shared__ __align__(16) float sbuf[128];   // [2 parities][64 partials]
    __shared__ float srho[Lt];
    const int b = blockIdx.x;
    const int idx = (b & 127) | ((b >> 8) << 7);
    if (((b >> 7) & 1) == 0) fwd_body(aT, idx, sbuf, srho);
    else                     bwd_body(bT, idx, sbuf, srho);
}

// column sums of clip(a)*clip(b) -> inv[j]; block owns 4 rows of a^T/b^T
__global__ void __launch_bounds__(512, 2) k_colsum(const float* __restrict__ aT,
                                                   const float* __restrict__ bT,
                                                   float* __restrict__ inv) {
    __shared__ float4 swarp[16];
    const int t = threadIdx.x;
    const int j0 = blockIdx.x << 2;
    float s[4] = {0.f, 0.f, 0.f, 0.f};
#pragma unroll
    for (int jj = 0; jj < 4; ++jj) {
        const float4* a4 = (const float4*)aT + (size_t)(j0 + jj) * 1024;
        const float4* b4 = (const float4*)bT + (size_t)(j0 + jj) * 1024;
#pragma unroll
        for (int k2 = 0; k2 < 2; ++k2) {
            const int idx = t + (k2 << 9);
            const float4 av = __ldg(a4 + idx);
            const float4 bv = __ldg(b4 + idx);
            s[jj] += __saturatef(av.x) * __saturatef(bv.x)
                   + __saturatef(av.y) * __saturatef(bv.y)
                   + __saturatef(av.z) * __saturatef(bv.z)
                   + __saturatef(av.w) * __saturatef(bv.w);
        }
    }
#pragma unroll
    for (int off = 16; off; off >>= 1) {
        s[0] += __shfl_xor_sync(0xFFFFFFFFu, s[0], off);
        s[1] += __shfl_xor_sync(0xFFFFFFFFu, s[1], off);
        s[2] += __shfl_xor_sync(0xFFFFFFFFu, s[2], off);
        s[3] += __shfl_xor_sync(0xFFFFFFFFu, s[3], off);
    }
    if ((t & 31) == 0) swarp[t >> 5] = make_float4(s[0], s[1], s[2], s[3]);
    __syncthreads();
    if (t == 0) {
        float4 v = swarp[0];
#pragma unroll
        for (int w = 1; w < 16; ++w) {
            float4 q = swarp[w];
            v.x += q.x; v.y += q.y; v.z += q.z; v.w += q.w;
        }
        inv[j0] = 1.0f / v.x; inv[j0 + 1] = 1.0f / v.y;
        inv[j0 + 2] = 1.0f / v.z; inv[j0 + 3] = 1.0f / v.w;
    }
}

// fused epilogue: p + d + alpha/beta std-layout, all from aT/bT tiles.
__global__ void k_out(const float* __restrict__ aT, const float* __restrict__ bT,
                      const float* __restrict__ inv,
                      float* __restrict__ p, float* __restrict__ d,
                      float* __restrict__ aStd, float* __restrict__ bStd) {
    const int bi = blockIdx.y, bj = blockIdx.x;
    if (bj < bi) return;
    __shared__ float PA[32][33], PB[32][33];
    __shared__ float AA[32][33], BA[32][33];
    __shared__ float AB[32][33], BB[32][33];
    const int tx = threadIdx.x & 31;
    const int ty0 = threadIdx.x >> 5;   // 0..7
    const bool diagBlk = (bi == bj);
#pragma unroll
    for (int k2 = 0; k2 < 4; ++k2) {
        const int y = ty0 + (k2 << 3);
        const int ja = (bi << 5) + y;
        const size_t offA = (size_t)ja * Nn + (bj << 5) + tx;
        const float av = __ldg(aT + offA);
        const float bv = __ldg(bT + offA);
        AA[y][tx] = av; BA[y][tx] = bv;
        PA[y][tx] = __saturatef(av) * __saturatef(bv) * __ldg(inv + ja);
        if (!diagBlk) {
            const int jb = (bj << 5) + y;
            const size_t offB = (size_t)jb * Nn + (bi << 5) + tx;
            const float av2 = __ldg(aT + offB);
            const float bv2 = __ldg(bT + offB);
            AB[y][tx] = av2; BB[y][tx] = bv2;
            PB[y][tx] = __saturatef(av2) * __saturatef(bv2) * __ldg(inv + jb);
        }
    }
    __syncthreads();
#pragma unroll
    for (int k2 = 0; k2 < 4; ++k2) {
        const int y = ty0 + (k2 << 3);
        const size_t o1 = (size_t)((bj << 5) + y) * Nn + (bi << 5) + tx;
        p[o1] = PA[tx][y];
        if (aStd) { aStd[o1] = AA[tx][y]; bStd[o1] = BA[tx][y]; }
        if (!diagBlk) {
            const size_t o2 = (size_t)((bi << 5) + y) * Nn + (bj << 5) + tx;
            p[o2] = PB[tx][y];
            if (aStd) { aStd[o2] = AB[tx][y]; bStd[o2] = BB[tx][y]; }
        }
    }
    if (d == nullptr) return;
    __syncthreads();
#pragma unroll
    for (int k2 = 0; k2 < 4; ++k2) {
        const int y = ty0 + (k2 << 3);
        PA[y][tx] = __logf(fmaxf(PA[y][tx], EPSF));
        if (!diagBlk) PB[y][tx] = __logf(fmaxf(PB[y][tx], EPSF));
    }
    __syncthreads();
    float (*LB)[33] = diagBlk ? PA : PB;
#pragma unroll
    for (int k2 = 0; k2 < 4; ++k2) {
        const int y = ty0 + (k2 << 3);
        float dv = -0.5f * (LB[tx][y] + PA[y][tx]);
        if (diagBlk && y == tx) dv = 0.0f;
        d[(size_t)((bi << 5) + y) * Nn + (bj << 5) + tx] = dv;
        if (!diagBlk)
            d[(size_t)((bj << 5) + y) * Nn + (bi << 5) + tx]
                = -0.5f * (PA[tx][y] + LB[y][tx]);
    }
}

extern "C" void kernel_launch(void* const* d_in, const int* in_sizes, int n_in,
                              void* d_out, int out_size) {
    const int* h = (const int*)d_in[0];
    const float* m = (const float*)d_in[1];
    float* out = (float*)d_out;

    void* sym;
    uint32_t* pk; float *rho, *aT, *bT, *inv;
    cudaGetSymbolAddress(&sym, g_pk);  pk  = (uint32_t*)sym;
    cudaGetSymbolAddress(&sym, g_rho); rho = (float*)sym;
    cudaGetSymbolAddress(&sym, g_aT);  aT  = (float*)sym;
    cudaGetSymbolAddress(&sym, g_bT);  bT  = (float*)sym;
    cudaGetSymbolAddress(&sym, g_inv); inv = (float*)sym;

    float *pOut, *dOut, *alphaStd, *betaStd;
    size_t osz = (size_t)out_size;
    if (osz >= 4 * NNsz) {
        pOut = out; dOut = out + NNsz;
        alphaStd = out + 2 * NNsz; betaStd = out + 3 * NNsz;
    } else if (osz >= 2 * NNsz) {
        pOut = out; dOut = out + NNsz; alphaStd = nullptr; betaStd = nullptr;
    } else {
        pOut = out; dOut = nullptr; alphaStd = nullptr; betaStd = nullptr;
    }

    k_rho<<<1, 256>>>(rho, m);
    k_pack<<<Lt, 128>>>(h, pk);
    k_main<<<2048, 512>>>(aT, bT);
    k_colsum<<<Nn / 4, 512>>>(aT, bT, inv);
    dim3 g2(Nn / 32, Nn / 32);
    k_out<<<g2, 256>>>(aT, bT, inv, pOut, dOut, alphaStd, betaStd);
}

// round 16
// speedup vs baseline: 1.0230x; 1.0171x over previous
#include <cuda_runtime.h>
#include <math.h>
#include <stdint.h>

#define Nn 4096
#define Lt 256
#define TLt 128
#define MUc 0.001f
#define Ac 0.999f          /* 1-mu */
#define NM1 4095.0f
#define INV_NM1 (1.0f/4095.0f)
#define EPSF 2.2204460492503131e-16f
#define NNsz ((size_t)Nn*(size_t)Nn)

typedef unsigned long long ull;

// ---- scratch (device globals; no allocations allowed) ----
__device__ __align__(16) uint32_t g_pk[Lt * 128];  // h packed to bits
__device__ float g_rho[Lt];
__device__ float g_inv[Nn];              // 1 / colsum of clip(a)*clip(b)
__device__ float g_aT[NNsz];             // alpha transposed
__device__ float g_bT[NNsz];             // beta transposed

// ---- packed f32x2 helpers ----
__device__ __forceinline__ ull pk2(float lo, float hi) {
    ull r; asm("mov.b64 %0,{%1,%2};" : "=l"(r) : "f"(lo), "f"(hi)); return r;
}
__device__ __forceinline__ void up2(ull v, float& lo, float& hi) {
    asm("mov.b64 {%0,%1},%2;" : "=f"(lo), "=f"(hi) : "l"(v));
}
__device__ __forceinline__ ull ffma2(ull a, ull b, ull c) {
    ull d; asm("fma.rn.f32x2 %0,%1,%2,%3;" : "=l"(d) : "l"(a), "l"(b), "l"(c)); return d;
}
__device__ __forceinline__ ull fmul2(ull a, ull b) {
    ull d; asm("mul.rn.f32x2 %0,%1,%2;" : "=l"(d) : "l"(a), "l"(b)); return d;
}
__device__ __forceinline__ ull fadd2(ull a, ull b) {
    ull d; asm("add.rn.f32x2 %0,%1,%2;" : "=l"(d) : "l"(a), "l"(b)); return d;
}
__device__ __forceinline__ float frcp_fast(float x) {
    float r; asm("rcp.approx.f32 %0,%1;" : "=f"(r) : "f"(x)); return r;
}

// rho[l] = -expm1(-n_e * m[l]),  n_e = 4*10000/4096 = 9.765625
__global__ void k_rho(float* __restrict__ rho, const float* __restrict__ m) {
    int t = threadIdx.x;
    if (t < Lt) rho[t] = -expm1f(-9.765625f * m[t]);
}

// pack h rows into bitmasks: bit (i&31) of word i>>5
__global__ void k_pack(const int* __restrict__ h, uint32_t* __restrict__ pk) {
    const int l = blockIdx.x;
    const int w = threadIdx.x;           // 0..127
    const int* row = h + (size_t)l * Nn + w * 32;
    uint32_t v = 0;
#pragma unroll
    for (int b = 0; b < 32; ++b) v |= ((uint32_t)(row[b] & 1)) << b;
    pk[l * 128 + w] = v;
}

// ---- lean one-barrier block sum of 4 partials (512 threads).
__device__ __forceinline__ float4 blockSum4v2(float s0, float s1, float s2, float s3,
                                              float* sbuf, int t, int par) {
    const int lane = t & 31, w = t >> 5;
    const bool hi16 = (lane & 16) != 0, hi8 = (lane & 8) != 0;
    float tA = __shfl_xor_sync(0xFFFFFFFFu, hi16 ? s0 : s2, 16);
    float tB = __shfl_xor_sync(0xFFFFFFFFu, hi16 ? s1 : s3, 16);
    const float x = hi16 ? (s2 + tA) : (s0 + tA);
    const float y = hi16 ? (s3 + tB) : (s1 + tB);
    float tC = __shfl_xor_sync(0xFFFFFFFFu, hi8 ? x : y, 8);
    float z = (hi8 ? y : x) + tC;
    z += __shfl_xor_sync(0xFFFFFFFFu, z, 4);
    z += __shfl_xor_sync(0xFFFFFFFFu, z, 2);
    z += __shfl_xor_sync(0xFFFFFFFFu, z, 1);
    float* buf = sbuf + (par << 6);
    if ((lane & 7) == 0) buf[(w << 2) + (lane >> 3)] = z;
    __syncthreads();
    float v = buf[lane] + buf[lane + 32];          // idx = w*4+c, c = idx&3
    v += __shfl_xor_sync(0xFFFFFFFFu, v, 4);
    v += __shfl_xor_sync(0xFFFFFFFFu, v, 8);
    v += __shfl_xor_sync(0xFFFFFFFFu, v, 16);
    float4 r;
    r.x = __shfl_sync(0xFFFFFFFFu, v, 0, 4);
    r.y = __shfl_sync(0xFFFFFFFFu, v, 1, 4);
    r.z = __shfl_sync(0xFFFFFFFFu, v, 2, 4);
    r.w = __shfl_sync(0xFFFFFFFFu, v, 3, 4);
    return r;
}

// diag fix: subtract diag values from packed sums AND zero state lanes.
__device__ __forceinline__ void diag_fix_fwd(ull& a0, ull& a1, ull& b2, ull& b3,
                                             ull& s0, ull& s1) {
    float lo, hi, sl, sh;
    up2(s0, sl, sh);
    up2(a0, lo, hi); sl -= lo; a0 = pk2(0.f, hi);
    up2(a1, lo, hi); sh -= hi; a1 = pk2(lo, 0.f);
    s0 = pk2(sl, sh);
    up2(s1, sl, sh);
    up2(b2, lo, hi); sl -= lo; b2 = pk2(0.f, hi);
    up2(b3, lo, hi); sh -= hi; b3 = pk2(lo, 0.f);
    s1 = pk2(sl, sh);
}
__device__ __forceinline__ void diag_zero(ull& a0, ull& a1, ull& b2, ull& b3) {
    a0 &= 0xFFFFFFFF00000000ull;  // zero lo lane
    a1 &= 0x00000000FFFFFFFFull;  // zero hi lane
    b2 &= 0xFFFFFFFF00000000ull;
    b3 &= 0x00000000FFFFFFFFull;
}

// transposed final store: thread owns rows r0..r0+7, cols j0..j0+3
__device__ __forceinline__ void store_T(float* __restrict__ xT, const ull st[8][2],
                                        int j0, int r0) {
#pragma unroll
    for (int c = 0; c < 4; ++c) {
        float v[8];
#pragma unroll
        for (int r = 0; r < 8; ++r) {
            float lo, hi; up2(st[r][c >> 1], lo, hi);
            v[r] = (c & 1) ? hi : lo;
        }
        float* base = xT + (size_t)(j0 + c) * Nn + r0;
        *(float4*)base       = make_float4(v[0], v[1], v[2], v[3]);
        *(float4*)(base + 4) = make_float4(v[4], v[5], v[6], v[7]);
    }
}

// Precompute packed emission coefficient table for this block's 4 columns.
// sE[s*4 + {0,1,2,3}] = E0p0, E1p0, E0p1, E1p1 at step-row srow(s).
// Block-uniform: hj depends only on j0 and the row.
__device__ __forceinline__ void precompE(ull* sE, int nSteps, int rowBase,
                                         int rowStride, int jWord, int jSh, int t) {
    for (int s = t; s < nSteps; s += 512) {
        const int lr = rowBase + s * rowStride;
        const uint32_t hj = (__ldg(g_pk + lr * 128 + jWord) >> jSh) & 0xFu;
        const float e0a = (hj & 1u) ? MUc : Ac, e1a = (hj & 1u) ? Ac : MUc;
        const float e0b = (hj & 2u) ? MUc : Ac, e1b = (hj & 2u) ? Ac : MUc;
        const float e0c = (hj & 4u) ? MUc : Ac, e1c = (hj & 4u) ? Ac : MUc;
        const float e0d = (hj & 8u) ? MUc : Ac, e1d = (hj & 8u) ? Ac : MUc;
        ull* e = sE + (s << 2);
        e[0] = pk2(e0a, e0b); e[1] = pk2(e1a, e1b);
        e[2] = pk2(e0c, e0d); e[3] = pk2(e1c, e1d);
    }
}

// ---------------- forward body: 129 steps resident in registers ----------------
__device__ __forceinline__ void fwd_body(float* __restrict__ aT, int blk,
                                         float* sbuf, float* srho, ull* sE) {
    const int t = threadIdx.x;
    const int j0 = blk << 2;
    const int r0 = t << 3;
    if (t < Lt) srho[t] = g_rho[t];

    const int wWord = r0 >> 5, wSh = r0 & 31;
    const int jWord = j0 >> 5, jSh = j0 & 31;
    const bool isDiagT = (t == (j0 >> 3));
    const bool diagHi = (j0 & 7) != 0;   // diag rows 4..7 vs 0..3

    precompE(sE, TLt + 1, 0, 1, jWord, jSh, t);

    ull st[8][2];
#pragma unroll
    for (int r = 0; r < 8; ++r) { st[r][0] = 0ull; st[r][1] = 0ull; }
    float4 tot = make_float4(1.f, 1.f, 1.f, 1.f);   // dummy; step0 uses w=0
    __syncthreads();

    for (int step = 0; step <= TLt; ++step) {
        const uint32_t hb = __ldg(g_pk + step * 128 + wWord) >> wSh;
        const ull* Ep = sE + (step << 2);
        const ull E0p0 = Ep[0], E1p0 = Ep[1], E0p1 = Ep[2], E1p1 = Ep[3];

        float wv, cst;
        if (step == 0) { wv = 0.0f; cst = INV_NM1; }
        else { const float r = srho[step - 1]; wv = 1.0f - r; cst = r * INV_NM1; }

        const ull wp0 = pk2(wv * frcp_fast(tot.x), wv * frcp_fast(tot.y));
        const ull wp1 = pk2(wv * frcp_fast(tot.z), wv * frcp_fast(tot.w));
        const ull cstp = pk2(cst, cst);

        ull sm0a = 0ull, sm0b = 0ull, sm1a = 0ull, sm1b = 0ull;
#pragma unroll
        for (int r = 0; r < 8; ++r) {
            const bool hi = (hb >> r) & 1u;
            const ull ea = hi ? E1p0 : E0p0;
            const ull eb = hi ? E1p1 : E0p1;
            const ull o0 = fmul2(ffma2(st[r][0], wp0, cstp), ea);
            const ull o1 = fmul2(ffma2(st[r][1], wp1, cstp), eb);
            st[r][0] = o0; st[r][1] = o1;
            if (r & 1) { sm0b = fadd2(sm0b, o0); sm1b = fadd2(sm1b, o1); }
            else       { sm0a = fadd2(sm0a, o0); sm1a = fadd2(sm1a, o1); }
        }
        ull sm0 = fadd2(sm0a, sm0b), sm1 = fadd2(sm1a, sm1b);
        if (isDiagT) {
            if (diagHi) diag_fix_fwd(st[4][0], st[5][0], st[6][1], st[7][1], sm0, sm1);
            else        diag_fix_fwd(st[0][0], st[1][0], st[2][1], st[3][1], sm0, sm1);
        }
        if (step < TLt) {
            float a0, a1, a2, a3;
            up2(sm0, a0, a1); up2(sm1, a2, a3);
            tot = blockSum4v2(a0, a1, a2, a3, sbuf, t, step & 1);
        }
    }
    store_T(aT, st, j0, r0);
}

// ---------------- backward body: u-state (u = theta o beta), deferred K --------
__device__ __forceinline__ void bwd_body(float* __restrict__ bT, int blk,
                                         float* sbuf, float* srho, ull* sE) {
    const int t = threadIdx.x;
    const int j0 = blk << 2;
    const int r0 = t << 3;
    if (t < Lt) srho[t] = g_rho[t];

    const int wWord = r0 >> 5, wSh = r0 & 31;
    const int jWord = j0 >> 5, jSh = j0 & 31;
    const bool isDiagT = (t == (j0 >> 3));
    const bool diagHi = (j0 & 7) != 0;
    const int NB = Lt - 1 - TLt;  // 127

    precompE(sE, NB, Lt - 1, -1, jWord, jSh, t);

    ull st[8][2];
    const ull one2 = pk2(1.0f, 1.0f);
#pragma unroll
    for (int r = 0; r < 8; ++r) { st[r][0] = one2; st[r][1] = one2; }
    __syncthreads();

    ull kp0 = 0ull, kp1 = 0ull;   // k=0: v = 0*st + 1  (beta_0 = 1 offdiag)
    ull rp = one2;
    for (int k = 0; k < NB; ++k) {
        const uint32_t hb = __ldg(g_pk + (Lt - 1 - k) * 128 + wWord) >> wSh;
        const ull* Ep = sE + (k << 2);
        const ull E0p0 = Ep[0], E1p0 = Ep[1], E0p1 = Ep[2], E1p1 = Ep[3];

        ull sm0a = 0ull, sm0b = 0ull, sm1a = 0ull, sm1b = 0ull;
#pragma unroll
        for (int r = 0; r < 8; ++r) {
            const bool hi = (hb >> r) & 1u;
            const ull ea = hi ? E1p0 : E0p0;
            const ull eb = hi ? E1p1 : E0p1;
            const ull u0 = fmul2(ea, ffma2(st[r][0], kp0, rp));
            const ull u1 = fmul2(eb, ffma2(st[r][1], kp1, rp));
            st[r][0] = u0; st[r][1] = u1;
            if (r & 1) { sm0b = fadd2(sm0b, u0); sm1b = fadd2(sm1b, u1); }
            else       { sm0a = fadd2(sm0a, u0); sm1a = fadd2(sm1a, u1); }
        }
        ull sm0 = fadd2(sm0a, sm0b), sm1 = fadd2(sm1a, sm1b);
        if (isDiagT) {
            if (diagHi) diag_fix_fwd(st[4][0], st[5][0], st[6][1], st[7][1], sm0, sm1);
            else        diag_fix_fwd(st[0][0], st[1][0], st[2][1], st[3][1], sm0, sm1);
        }
        float a0, a1, a2, a3;
        up2(sm0, a0, a1); up2(sm1, a2, a3);
        const float4 tot = blockSum4v2(a0, a1, a2, a3, sbuf, t, k & 1);

        const float rr = srho[Lt - 2 - k];
        const float ks = (1.0f - rr) * NM1;
        kp0 = pk2(ks * frcp_fast(tot.x), ks * frcp_fast(tot.y));
        kp1 = pk2(ks * frcp_fast(tot.z), ks * frcp_fast(tot.w));
        rp = pk2(rr, rr);
    }
    // final: beta = K_last*u + r_last; zero diag; store
#pragma unroll
    for (int r = 0; r < 8; ++r) {
        st[r][0] = ffma2(st[r][0], kp0, rp);
        st[r][1] = ffma2(st[r][1], kp1, rp);
    }
    if (isDiagT) {
        if (diagHi) diag_zero(st[4][0], st[5][0], st[6][1], st[7][1]);
        else        diag_zero(st[0][0], st[1][0], st[2][1], st[3][1]);
    }
    store_T(bT, st, j0, r0);
}

// merged: blocks [0,1024) run forward, [1024,2048) run backward
__global__ void __launch_bounds__(512, 2) k_main(float* __restrict__ aT,
                                                 float* __restrict__ bT) {
    __shared__ __align__(16) float sbuf[128];   // [2 parities][64 partials]
    __shared__ float srho[Lt];
    __shared__ __align__(16) ull sE[(TLt + 1) * 4];  // per-step packed emissions
    if (blockIdx.x < 1024) fwd_body(aT, blockIdx.x, sbuf, srho, sE);
    else                   bwd_body(bT, blockIdx.x - 1024, sbuf, srho, sE);
}

// column sums of clip(a)*clip(b) -> inv[j]; block owns 4 rows of a^T/b^T
__global__ void __launch_bounds__(512, 2) k_colsum(const float* __restrict__ aT,
                                                   const float* __restrict__ bT,
                                                   float* __restrict__ inv) {
    __shared__ float4 swarp[16];
    const int t = threadIdx.x;
    const int j0 = blockIdx.x << 2;
    float s[4] = {0.f, 0.f, 0.f, 0.f};
#pragma unroll
    for (int jj = 0; jj < 4; ++jj) {
        const float4* a4 = (const float4*)aT + (size_t)(j0 + jj) * 1024;
        const float4* b4 = (const float4*)bT + (size_t)(j0 + jj) * 1024;
#pragma unroll
        for (int k2 = 0; k2 < 2; ++k2) {
            const int idx = t + (k2 << 9);
            const float4 av = __ldg(a4 + idx);
            const float4 bv = __ldg(b4 + idx);
            s[jj] += __saturatef(av.x) * __saturatef(bv.x)
                   + __saturatef(av.y) * __saturatef(bv.y)
                   + __saturatef(av.z) * __saturatef(bv.z)
                   + __saturatef(av.w) * __saturatef(bv.w);
        }
    }
#pragma unroll
    for (int off = 16; off; off >>= 1) {
        s[0] += __shfl_xor_sync(0xFFFFFFFFu, s[0], off);
        s[1] += __shfl_xor_sync(0xFFFFFFFFu, s[1], off);
        s[2] += __shfl_xor_sync(0xFFFFFFFFu, s[2], off);
        s[3] += __shfl_xor_sync(0xFFFFFFFFu, s[3], off);
    }
    if ((t & 31) == 0) swarp[t >> 5] = make_float4(s[0], s[1], s[2], s[3]);
    __syncthreads();
    if (t == 0) {
        float4 v = swarp[0];
#pragma unroll
        for (int w = 1; w < 16; ++w) {
            float4 q = swarp[w];
            v.x += q.x; v.y += q.y; v.z += q.z; v.w += q.w;
        }
        inv[j0] = 1.0f / v.x; inv[j0 + 1] = 1.0f / v.y;
        inv[j0 + 2] = 1.0f / v.z; inv[j0 + 3] = 1.0f / v.w;
    }
}

// fused epilogue: p + d + alpha/beta std-layout, all from aT/bT tiles.
__global__ void k_out(const float* __restrict__ aT, const float* __restrict__ bT,
                      const float* __restrict__ inv,
                      float* __restrict__ p, float* __restrict__ d,
                      float* __restrict__ aStd, float* __restrict__ bStd) {
    const int bi = blockIdx.y, bj = blockIdx.x;
    if (bj < bi) return;
    __shared__ float PA[32][33], PB[32][33];
    __shared__ float AA[32][33], BA[32][33];
    __shared__ float AB[32][33], BB[32][33];
    const int tx = threadIdx.x & 31;
    const int ty0 = threadIdx.x >> 5;   // 0..7
    const bool diagBlk = (bi == bj);
#pragma unroll
    for (int k2 = 0; k2 < 4; ++k2) {
        const int y = ty0 + (k2 << 3);
        const int ja = (bi << 5) + y;
        const size_t offA = (size_t)ja * Nn + (bj << 5) + tx;
        const float av = __ldg(aT + offA);
        const float bv = __ldg(bT + offA);
        AA[y][tx] = av; BA[y][tx] = bv;
        PA[y][tx] = __saturatef(av) * __saturatef(bv) * __ldg(inv + ja);
        if (!diagBlk) {
            const int jb = (bj << 5) + y;
            const size_t offB = (size_t)jb * Nn + (bi << 5) + tx;
            const float av2 = __ldg(aT + offB);
            const float bv2 = __ldg(bT + offB);
            AB[y][tx] = av2; BB[y][tx] = bv2;
            PB[y][tx] = __saturatef(av2) * __saturatef(bv2) * __ldg(inv + jb);
        }
    }
    __syncthreads();
#pragma unroll
    for (int k2 = 0; k2 < 4; ++k2) {
        const int y = ty0 + (k2 << 3);
        const size_t o1 = (size_t)((bj << 5) + y) * Nn + (bi << 5) + tx;
        p[o1] = PA[tx][y];
        if (aStd) { aStd[o1] = AA[tx][y]; bStd[o1] = BA[tx][y]; }
        if (!diagBlk) {
            const size_t o2 = (size_t)((bi << 5) + y) * Nn + (bj << 5) + tx;
            p[o2] = PB[tx][y];
            if (aStd) { aStd[o2] = AB[tx][y]; bStd[o2] = BB[tx][y]; }
        }
    }
    if (d == nullptr) return;
    __syncthreads();
#pragma unroll
    for (int k2 = 0; k2 < 4; ++k2) {
        const int y = ty0 + (k2 << 3);
        PA[y][tx] = __logf(fmaxf(PA[y][tx], EPSF));
        if (!diagBlk) PB[y][tx] = __logf(fmaxf(PB[y][tx], EPSF));
    }
    __syncthreads();
    float (*LB)[33] = diagBlk ? PA : PB;
#pragma unroll
    for (int k2 = 0; k2 < 4; ++k2) {
        const int y = ty0 + (k2 << 3);
        float dv = -0.5f * (LB[tx][y] + PA[y][tx]);
        if (diagBlk && y == tx) dv = 0.0f;
        d[(size_t)((bi << 5) + y) * Nn + (bj << 5) + tx] = dv;
        if (!diagBlk)
            d[(size_t)((bj << 5) + y) * Nn + (bi << 5) + tx]
                = -0.5f * (PA[tx][y] + LB[y][tx]);
    }
}

extern "C" void kernel_launch(void* const* d_in, const int* in_sizes, int n_in,
                              void* d_out, int out_size) {
    const int* h = (const int*)d_in[0];
    const float* m = (const float*)d_in[1];
    float* out = (float*)d_out;

    void* sym;
    uint32_t* pk; float *rho, *aT, *bT, *inv;
    cudaGetSymbolAddress(&sym, g_pk);  pk  = (uint32_t*)sym;
    cudaGetSymbolAddress(&sym, g_rho); rho = (float*)sym;
    cudaGetSymbolAddress(&sym, g_aT);  aT  = (float*)sym;
    cudaGetSymbolAddress(&sym, g_bT);  bT  = (float*)sym;
    cudaGetSymbolAddress(&sym, g_inv); inv = (float*)sym;

    float *pOut, *dOut, *alphaStd, *betaStd;
    size_t osz = (size_t)out_size;
    if (osz >= 4 * NNsz) {
        pOut = out; dOut = out + NNsz;
        alphaStd = out + 2 * NNsz; betaStd = out + 3 * NNsz;
    } else if (osz >= 2 * NNsz) {
        pOut = out; dOut = out + NNsz; alphaStd = nullptr; betaStd = nullptr;
    } else {
        pOut = out; dOut = nullptr; alphaStd = nullptr; betaStd = nullptr;
    }

    k_rho<<<1, 256>>>(rho, m);
    k_pack<<<Lt, 128>>>(h, pk);
    k_main<<<2048, 512>>>(aT, bT);
    k_colsum<<<Nn / 4, 512>>>(aT, bT, inv);
    dim3 g2(Nn / 32, Nn / 32);
    k_out<<<g2, 256>>>(aT, bT, inv, pOut, dOut, alphaStd, betaStd);
}